// round 2
// baseline (speedup 1.0000x reference)
#include <cuda_runtime.h>

// Problem constants (match reference: LATENT_DIM=16, N_PARAMS=2, POLY_ORDER=3)
#define NVARS   18
#define NPOLY   1330          // 1 + 18 + 171 + 1140
#define BATCH_N 131072
#define TPB     256           // threads per block; each thread computes 2 rows

typedef unsigned long long u64;

// ---- Blackwell packed-fp32 primitives (f32x2, 2x FFMA throughput) ----
__device__ __forceinline__ u64 ffma2(u64 a, u64 b, u64 c) {
    u64 d;
    asm("fma.rn.f32x2 %0, %1, %2, %3;" : "=l"(d) : "l"(a), "l"(b), "l"(c));
    return d;
}
__device__ __forceinline__ u64 fmul2(u64 a, u64 b) {
    u64 d;
    asm("mul.rn.f32x2 %0, %1, %2;" : "=l"(d) : "l"(a), "l"(b));
    return d;
}
__device__ __forceinline__ u64 pack2(float lo, float hi) {
    u64 d;
    asm("mov.b64 %0, {%1, %2};" : "=l"(d) : "f"(lo), "f"(hi));
    return d;
}
__device__ __forceinline__ float2 unpack2(u64 v) {
    float2 r;
    asm("mov.b64 {%0, %1}, %2;" : "=f"(r.x), "=f"(r.y) : "l"(v));
    return r;
}

// Each thread handles 2 consecutive batch rows packed into f32x2 lanes.
// W (= big_xi * mask) lives in SMEM pre-duplicated as {w,w} pairs so every
// weight use is one broadcast LDS (no per-use packing). Monomials are walked
// in combinations_with_replacement lex order => W pointers just increment.
__global__ void __launch_bounds__(TPB, 1)
vindy_kernel(const float* __restrict__ z,
             const float* __restrict__ betas,
             const float* __restrict__ big_xi,
             const float* __restrict__ mask,
             float* __restrict__ out)
{
    extern __shared__ u64 Wdup[];   // [NPOLY][NVARS] duplicated pairs, 191520 B

    const int tid = threadIdx.x;

    // Cooperative staging of W with lane duplication
    for (int i = tid; i < NPOLY * NVARS; i += TPB) {
        const float w = big_xi[i] * mask[i];
        Wdup[i] = pack2(w, w);
    }

    const int pairIdx = blockIdx.x * TPB + tid;
    const int r0 = pairIdx * 2;
    const int r1 = r0 + 1;

    // x = concat(z, betas), packed {row0, row1}. Dynamic indexing below =>
    // compiler places this in local memory (L1-resident, latency hidden).
    u64 xp[NVARS];
    {
        const float4* z0 = reinterpret_cast<const float4*>(z + (size_t)r0 * 16);
        const float4* z1 = reinterpret_cast<const float4*>(z + (size_t)r1 * 16);
        #pragma unroll
        for (int q = 0; q < 4; ++q) {
            const float4 a = z0[q];
            const float4 b = z1[q];
            xp[q * 4 + 0] = pack2(a.x, b.x);
            xp[q * 4 + 1] = pack2(a.y, b.y);
            xp[q * 4 + 2] = pack2(a.z, b.z);
            xp[q * 4 + 3] = pack2(a.w, b.w);
        }
        const float2 b0 = reinterpret_cast<const float2*>(betas)[r0];
        const float2 b1 = reinterpret_cast<const float2*>(betas)[r1];
        xp[16] = pack2(b0.x, b1.x);
        xp[17] = pack2(b0.y, b1.y);
    }

    __syncthreads();

    // Accumulators init = bias row (theta col 0 == 1)
    u64 acc[NVARS];
    #pragma unroll
    for (int j = 0; j < NVARS; ++j) acc[j] = Wdup[j];

    // Section pointers: rows [1,19) deg1, [19,190) deg2, [190,1330) deg3.
    const u64* w1 = Wdup + 1 * NVARS;
    const u64* w2 = Wdup + (1 + NVARS) * NVARS;
    const u64* w3 = Wdup + (1 + NVARS + (NVARS * (NVARS + 1)) / 2) * NVARS;

    #pragma unroll 1
    for (int a = 0; a < NVARS; ++a) {
        const u64 xa = xp[a];
        #pragma unroll
        for (int j = 0; j < NVARS; ++j) acc[j] = ffma2(xa, w1[j], acc[j]);
        w1 += NVARS;

        #pragma unroll 1
        for (int b = a; b < NVARS; ++b) {
            const u64 pab = fmul2(xa, xp[b]);
            #pragma unroll
            for (int j = 0; j < NVARS; ++j) acc[j] = ffma2(pab, w2[j], acc[j]);
            w2 += NVARS;

            #pragma unroll 1
            for (int c = b; c < NVARS; ++c) {
                const u64 pabc = fmul2(pab, xp[c]);
                #pragma unroll
                for (int j = 0; j < NVARS; ++j) acc[j] = ffma2(pabc, w3[j], acc[j]);
                w3 += NVARS;
            }
        }
    }

    // Write out [BATCH, 18] fp32
    float* o0 = out + (size_t)r0 * NVARS;
    float* o1 = out + (size_t)r1 * NVARS;
    #pragma unroll
    for (int j = 0; j < NVARS; ++j) {
        const float2 v = unpack2(acc[j]);
        o0[j] = v.x;
        o1[j] = v.y;
    }
}

extern "C" void kernel_launch(void* const* d_in, const int* in_sizes, int n_in,
                              void* d_out, int out_size)
{
    const float* z      = (const float*)d_in[0];
    const float* betas  = (const float*)d_in[1];
    const float* big_xi = (const float*)d_in[2];
    const float* mask   = (const float*)d_in[3];
    float* out = (float*)d_out;

    const int smem = NPOLY * NVARS * (int)sizeof(u64);  // 191520 B
    cudaFuncSetAttribute(vindy_kernel,
                         cudaFuncAttributeMaxDynamicSharedMemorySize, smem);

    const int grid = BATCH_N / (2 * TPB);  // 256 blocks
    vindy_kernel<<<grid, TPB, smem>>>(z, betas, big_xi, mask, out);
}